// round 16
// baseline (speedup 1.0000x reference)
#include <cuda_runtime.h>
#include <cuda_bf16.h>
#include <cstdint>

#define QSCALE 0.25503486f   // 32^-0.5 * log2(e): exp(s*SCALE) == exp2(s*QSCALE)

// ---- smem byte offsets ----
#define OFF_QH 0          // Qhi bf16 [128 rows][40]  (32 data + 8 pad -> 80B/row)
#define OFF_QL 10240      // Qlo
#define OFF_KS 20480      // K stages: 2 x (Khi[128][80] 10240 + Klo 10240)
#define OFF_VT 61440      // V bf16 ch-major [32][520]  (33,280)
#define OFF_SR 94720      // 128 floats: 1/rowsum
#define OFF_W  95232      // conv w 288 f
#define OFF_CB 96384      // conv b 32 f
#define SMEM_BYTES 96512
#define OFF_VF 0          // fp32 V [32][516] aliases Q/K in epilogue

#define L_OF(k) (((k) >> 3) * 64 + w2 * 8 + ((k) & 7))

#define MMA(d, a, b) asm volatile( \
  "mma.sync.aligned.m16n8k16.row.col.f32.bf16.bf16.f32 " \
  "{%0,%1,%2,%3}, {%4,%5,%6,%7}, {%8,%9}, {%0,%1,%2,%3};" \
  : "+f"((d)[0]), "+f"((d)[1]), "+f"((d)[2]), "+f"((d)[3]) \
  : "r"((a)[0]), "r"((a)[1]), "r"((a)[2]), "r"((a)[3]), "r"((b)[0]), "r"((b)[1]))

#define LDM4(r, addr) asm volatile( \
  "ldmatrix.sync.aligned.m8n8.x4.shared.b16 {%0,%1,%2,%3}, [%4];" \
  : "=r"((r)[0]), "=r"((r)[1]), "=r"((r)[2]), "=r"((r)[3]) : "r"(addr))

#define EX2(y, x) asm("ex2.approx.f32 %0, %1;" : "=f"(y) : "f"(x))

__device__ __forceinline__ uint32_t packpair(float a, float b, uint32_t& lo) {
    __nv_bfloat16 ah = __float2bfloat16(a), bh = __float2bfloat16(b);
    __nv_bfloat16 al = __float2bfloat16(a - __bfloat162float(ah));
    __nv_bfloat16 bl = __float2bfloat16(b - __bfloat162float(bh));
    lo = (uint32_t)__bfloat16_as_ushort(al) | ((uint32_t)__bfloat16_as_ushort(bl) << 16);
    return (uint32_t)__bfloat16_as_ushort(ah) | ((uint32_t)__bfloat16_as_ushort(bh) << 16);
}
__device__ __forceinline__ uint32_t packbf(float a, float b) {
    __nv_bfloat162 t = __floats2bfloat162_rn(a, b);
    return *reinterpret_cast<uint32_t*>(&t);
}

// ---------------------------------------------------------------------------
// CTA = (wh, qb): 128 q rows of window-head wh. 256 threads, 8 warps.
// R15 structure with K staged 128 keys at a time (2 chunks/stage, 2-stage
// ring) -> 4 syncs instead of 8, longer uninterrupted mma runs.
//   S chunk = Q(hi/lo) K(hi/lo)^T via mma.m16n8k16 (hh+hl+lh, 2-way ILP)
//   exp2 in regs (QSCALE folded, no max-sub) -> unnormalized e:
//   STG attn + rowsum accumulate; PV: e bf16 A-frags direct from S D-frags.
// Epilogue: rowsum reduce -> attn in-place rescale (L2-hot) -> fp32 V reload
//   (aliased smem) -> O/sum + LePE conv -> STG x.
// ---------------------------------------------------------------------------
__global__ __launch_bounds__(256, 2)
void fused_attn_mma(const float* __restrict__ qkv, const float* __restrict__ cw,
                    const float* __restrict__ cb, float* __restrict__ attn_out,
                    float* __restrict__ xout) {
    extern __shared__ char smem[];
    uint32_t sb = (uint32_t)__cvta_generic_to_shared(smem);
    float* Sr  = (float*)(smem + OFF_SR);
    float* Wsh = (float*)(smem + OFF_W);
    float* CBs = (float*)(smem + OFF_CB);
    float* Vf  = (float*)(smem + OFF_VF);

    int bx = blockIdx.x, wh = bx >> 2, qb = bx & 3;
    int n = wh >> 3, h = wh & 7, b = n >> 3, w2 = n & 7;
    int tid = threadIdx.x, lane = tid & 31, warp = tid >> 5;
    int g = lane >> 2, t = lane & 3;

    const float* Qg = qkv + (size_t)(0 + b) * 4096 * 256;
    const float* Kg = qkv + (size_t)(4 + b) * 4096 * 256;
    const float* Vg = qkv + (size_t)(8 + b) * 4096 * 256;

    // ---- prologue: Q hi/lo (QSCALE folded), V bf16, conv params ----
    {
        int row = tid >> 1, d0 = (tid & 1) * 16;
        int l = L_OF(qb * 128 + row);
        const float4* src = (const float4*)(Qg + (size_t)l * 256 + h * 32 + d0);
        uint32_t H[8], L[8];
        #pragma unroll
        for (int v4 = 0; v4 < 4; v4++) {
            float4 q = src[v4];
            q.x *= QSCALE; q.y *= QSCALE; q.z *= QSCALE; q.w *= QSCALE;
            H[2*v4]   = packpair(q.x, q.y, L[2*v4]);
            H[2*v4+1] = packpair(q.z, q.w, L[2*v4+1]);
        }
        char* qh = smem + OFF_QH + row * 80 + d0 * 2;
        char* ql = smem + OFF_QL + row * 80 + d0 * 2;
        *(uint4*)qh        = make_uint4(H[0], H[1], H[2], H[3]);
        *(uint4*)(qh + 16) = make_uint4(H[4], H[5], H[6], H[7]);
        *(uint4*)ql        = make_uint4(L[0], L[1], L[2], L[3]);
        *(uint4*)(ql + 16) = make_uint4(L[4], L[5], L[6], L[7]);
    }
    {   // V bf16 ch-major: warp covers 64 keys, lane = channel
        #pragma unroll 4
        for (int i = 0; i < 64; i += 2) {
            int k = warp * 64 + i;
            float v0 = Vg[(size_t)L_OF(k) * 256 + h * 32 + lane];
            float v1 = Vg[(size_t)L_OF(k + 1) * 256 + h * 32 + lane];
            *(uint32_t*)(smem + OFF_VT + lane * 1040 + k * 2) = packbf(v0, v1);
        }
    }
    for (int i = tid; i < 288; i += 256) Wsh[i] = cw[(h * 32) * 9 + i];
    if (tid < 32) CBs[tid] = cb[h * 32 + tid];

    // prefetch K stage 0 (128 rows; thread = one 16-float row-half)
    float4 pf[4];
    int krow = tid >> 1, kd0 = (tid & 1) * 16;
    {
        const float4* p = (const float4*)(Kg + (size_t)L_OF(krow) * 256 + h * 32 + kd0);
        pf[0] = p[0]; pf[1] = p[1]; pf[2] = p[2]; pf[3] = p[3];
    }
    __syncthreads();

    // Q A-frags (per warp, fixed)
    uint32_t aQh[2][4], aQl[2][4];
    {
        uint32_t laneQ = (uint32_t)((warp * 16 + (lane & 15)) * 80 + (lane >> 4) * 16);
        #pragma unroll
        for (int s = 0; s < 2; s++) {
            LDM4(aQh[s], sb + OFF_QH + s * 32 + laneQ);
            LDM4(aQl[s], sb + OFF_QL + s * 32 + laneQ);
        }
    }
    uint32_t laneK = (uint32_t)(((((lane >> 4) & 1) * 8) + (lane & 7)) * 80 + ((lane >> 3) & 1) * 16);
    uint32_t laneV = (uint32_t)(((((lane >> 4) & 1) * 8) + (lane & 7)) * 1040 + ((lane >> 3) & 1) * 16);

    float sumA = 0.f, sumB = 0.f;
    float oacc[4][4];
    #pragma unroll
    for (int i = 0; i < 4; i++)
        #pragma unroll
        for (int j = 0; j < 4; j++) oacc[i][j] = 0.f;

    float* attnp = attn_out + ((size_t)wh * 512 + qb * 128) * 512;

    for (int st = 0; st < 4; st++) {
        // ---- stage 128 prefetched K rows (hi/lo split); ONE sync/stage ----
        uint32_t stg = OFF_KS + (uint32_t)(st & 1) * 20480u;
        {
            uint32_t H[8], L[8];
            #pragma unroll
            for (int v4 = 0; v4 < 4; v4++) {
                H[2*v4]   = packpair(pf[v4].x, pf[v4].y, L[2*v4]);
                H[2*v4+1] = packpair(pf[v4].z, pf[v4].w, L[2*v4+1]);
            }
            char* dh = smem + stg + krow * 80 + kd0 * 2;
            *(uint4*)dh            = make_uint4(H[0], H[1], H[2], H[3]);
            *(uint4*)(dh + 16)     = make_uint4(H[4], H[5], H[6], H[7]);
            *(uint4*)(dh + 10240)  = make_uint4(L[0], L[1], L[2], L[3]);
            *(uint4*)(dh + 10256)  = make_uint4(L[4], L[5], L[6], L[7]);
        }
        __syncthreads();
        if (st < 3) {
            const float4* p = (const float4*)(Kg +
                (size_t)L_OF((st + 1) * 128 + krow) * 256 + h * 32 + kd0);
            pf[0] = p[0]; pf[1] = p[1]; pf[2] = p[2]; pf[3] = p[3];
        }

        #pragma unroll
        for (int sub = 0; sub < 2; sub++) {
            int c = st * 2 + sub;
            uint32_t khh = sb + stg + (uint32_t)sub * 5120u;
            uint32_t khl = khh + 10240u;

            // ---- S chunk: 48 mmas, nt0/nt1 chains interleaved ----
            float sacc[8][4];
            #pragma unroll
            for (int i = 0; i < 8; i++)
                #pragma unroll
                for (int j = 0; j < 4; j++) sacc[i][j] = 0.f;
            #pragma unroll
            for (int s = 0; s < 2; s++) {
                #pragma unroll
                for (int grp = 0; grp < 4; grp++) {
                    int nt0 = grp * 2;
                    uint32_t bh[4], bl[4];
                    LDM4(bh, khh + (uint32_t)nt0 * 640 + s * 32 + laneK);
                    LDM4(bl, khl + (uint32_t)nt0 * 640 + s * 32 + laneK);
                    MMA(sacc[nt0],     aQh[s], bh);
                    MMA(sacc[nt0 + 1], aQh[s], bh + 2);
                    MMA(sacc[nt0],     aQh[s], bl);
                    MMA(sacc[nt0 + 1], aQh[s], bl + 2);
                    MMA(sacc[nt0],     aQl[s], bh);
                    MMA(sacc[nt0 + 1], aQl[s], bh + 2);
                }
            }

            // ---- exp2 + rowsums + unnormalized attn STG ----
            #pragma unroll
            for (int nt = 0; nt < 8; nt++) {
                float e0, e1, e2, e3;
                EX2(e0, sacc[nt][0]); EX2(e1, sacc[nt][1]);
                EX2(e2, sacc[nt][2]); EX2(e3, sacc[nt][3]);
                sumA += e0 + e1; sumB += e2 + e3;
                sacc[nt][0] = e0; sacc[nt][1] = e1; sacc[nt][2] = e2; sacc[nt][3] = e3;
                float* p0 = attnp + (size_t)(warp * 16 + g) * 512 + c * 64 + nt * 8 + 2 * t;
                *(float2*)p0 = make_float2(e0, e1);
                *(float2*)(p0 + 8 * 512) = make_float2(e2, e3);
            }

            // ---- PV: S D-frags become A-frags; 16 mmas ----
            #pragma unroll
            for (int ks = 0; ks < 4; ks++) {
                uint32_t Ea[4] = {
                    packbf(sacc[2*ks][0],   sacc[2*ks][1]),
                    packbf(sacc[2*ks][2],   sacc[2*ks][3]),
                    packbf(sacc[2*ks+1][0], sacc[2*ks+1][1]),
                    packbf(sacc[2*ks+1][2], sacc[2*ks+1][3]) };
                uint32_t bv[4];
                LDM4(bv, sb + OFF_VT + (uint32_t)(c * 128 + ks * 32) + laneV);
                MMA(oacc[0], Ea, bv); MMA(oacc[1], Ea, bv + 2);
                LDM4(bv, sb + OFF_VT + 16640u + (uint32_t)(c * 128 + ks * 32) + laneV);
                MMA(oacc[2], Ea, bv); MMA(oacc[3], Ea, bv + 2);
            }
        }
        // no bottom sync: 2-stage ring + top sync make it redundant
    }

    // ---- rowsum reduce across the 4 lanes sharing a row ----
    sumA += __shfl_xor_sync(0xffffffffu, sumA, 1);
    sumA += __shfl_xor_sync(0xffffffffu, sumA, 2);
    sumB += __shfl_xor_sync(0xffffffffu, sumB, 1);
    sumB += __shfl_xor_sync(0xffffffffu, sumB, 2);
    float invA = 1.0f / sumA, invB = 1.0f / sumB;
    if (t == 0) { Sr[warp * 16 + g] = invA; Sr[warp * 16 + 8 + g] = invB; }
    __syncthreads();                 // all compute done; Sr ready; smem dead

    // ---- fp32 V reload into aliased smem (for exact LePE conv) ----
    #pragma unroll 4
    for (int i = 0; i < 64; i++) {
        int k = warp * 64 + i;
        Vf[lane * 516 + k] = Vg[(size_t)L_OF(k) * 256 + h * 32 + lane];
    }
    // ---- attn in-place rescale (L2-hot; 2 lines/iter for MLP) ----
    #pragma unroll 4
    for (int j = 0; j < 32; j++) {
        int idx = tid + j * 512;
        int row0 = idx >> 7, c40 = idx & 127;
        int row1 = (idx + 256) >> 7, c41 = (idx + 256) & 127;
        float* p0 = attnp + (size_t)row0 * 512 + c40 * 4;
        float* p1 = attnp + (size_t)row1 * 512 + c41 * 4;
        float4 v0 = *(float4*)p0;
        float4 v1 = *(float4*)p1;
        float i0 = Sr[row0], i1 = Sr[row1];
        v0.x *= i0; v0.y *= i0; v0.z *= i0; v0.w *= i0;
        v1.x *= i1; v1.y *= i1; v1.z *= i1; v1.w *= i1;
        *(float4*)p0 = v0;
        *(float4*)p1 = v1;
    }
    __syncthreads();                 // Vf ready

    // ---- epilogue: O/sum + LePE conv + STG x ----
    #pragma unroll
    for (int rsel = 0; rsel < 2; rsel++) {
        int R = warp * 16 + g + rsel * 8;
        int tg = qb * 128 + R;
        int hs = tg >> 3, ws = tg & 7;
        float inv = rsel ? invB : invA;
        int l = hs * 64 + w2 * 8 + ws;
        float* xp = xout + ((size_t)b * 4096 + l) * 256 + h * 32;
        #pragma unroll
        for (int ct = 0; ct < 4; ct++) {
            int ch0 = ct * 8 + 2 * t;
            float o0 = oacc[ct][2 * rsel]     * inv + CBs[ch0];
            float o1 = oacc[ct][2 * rsel + 1] * inv + CBs[ch0 + 1];
            #pragma unroll
            for (int dy = -1; dy <= 1; dy++) {
                if ((unsigned)(hs + dy) >= 64u) continue;
                #pragma unroll
                for (int dx = -1; dx <= 1; dx++) {
                    if ((unsigned)(ws + dx) >= 8u) continue;
                    int kk = tg + dy * 8 + dx, wi = (dy + 1) * 3 + (dx + 1);
                    o0 += Vf[ch0 * 516 + kk]       * Wsh[ch0 * 9 + wi];
                    o1 += Vf[(ch0 + 1) * 516 + kk] * Wsh[(ch0 + 1) * 9 + wi];
                }
            }
            *(float2*)(xp + ch0) = make_float2(o0, o1);
        }
    }
}

// ---------------------------------------------------------------------------
extern "C" void kernel_launch(void* const* d_in, const int* in_sizes, int n_in,
                              void* d_out, int out_size) {
    const float* qkv = (const float*)d_in[0];
    const float* cw  = (const float*)d_in[1];
    const float* cb  = (const float*)d_in[2];
    float* xout = (float*)d_out;
    float* attn = xout + (size_t)4 * 4096 * 256;    // x first, then attn

    cudaFuncSetAttribute(fused_attn_mma,
                         cudaFuncAttributeMaxDynamicSharedMemorySize, SMEM_BYTES);
    fused_attn_mma<<<1024, 256, SMEM_BYTES>>>(qkv, cw, cb, attn, xout);
}

// round 17
// speedup vs baseline: 1.0319x; 1.0319x over previous
#include <cuda_runtime.h>
#include <cuda_bf16.h>
#include <cstdint>

#define QSCALE 0.25503486f   // 32^-0.5 * log2(e): exp(s*SCALE) == exp2(s*QSCALE)

// ---- smem byte offsets ----
#define OFF_QH 0          // Qhi bf16 [128 rows][40]  (32 data + 8 pad)
#define OFF_QL 10240      // Qlo
#define OFF_KS 20480      // K stages: 2 x (Khi[64][40] 5120 + Klo 5120)
#define OFF_VT 40960      // V bf16 ch-major [32][520]  (33,280)
#define OFF_SR 74240      // 128 floats: 1/rowsum
#define OFF_W  74752      // conv w 288 f
#define OFF_CB 75904      // conv b 32 f
#define SMEM_BYTES 76032
#define OFF_VF 0          // fp32 V [32][516] aliases Q/K/VT in epilogue

#define L_OF(k) (((k) >> 3) * 64 + w2 * 8 + ((k) & 7))

#define MMA(d, a, b) asm volatile( \
  "mma.sync.aligned.m16n8k16.row.col.f32.bf16.bf16.f32 " \
  "{%0,%1,%2,%3}, {%4,%5,%6,%7}, {%8,%9}, {%0,%1,%2,%3};" \
  : "+f"((d)[0]), "+f"((d)[1]), "+f"((d)[2]), "+f"((d)[3]) \
  : "r"((a)[0]), "r"((a)[1]), "r"((a)[2]), "r"((a)[3]), "r"((b)[0]), "r"((b)[1]))

#define LDM4(r, addr) asm volatile( \
  "ldmatrix.sync.aligned.m8n8.x4.shared.b16 {%0,%1,%2,%3}, [%4];" \
  : "=r"((r)[0]), "=r"((r)[1]), "=r"((r)[2]), "=r"((r)[3]) : "r"(addr))

#define EX2(y, x) asm("ex2.approx.f32 %0, %1;" : "=f"(y) : "f"(x))

__device__ __forceinline__ uint32_t packpair(float a, float b, uint32_t& lo) {
    __nv_bfloat16 ah = __float2bfloat16(a), bh = __float2bfloat16(b);
    __nv_bfloat16 al = __float2bfloat16(a - __bfloat162float(ah));
    __nv_bfloat16 bl = __float2bfloat16(b - __bfloat162float(bh));
    lo = (uint32_t)__bfloat16_as_ushort(al) | ((uint32_t)__bfloat16_as_ushort(bl) << 16);
    return (uint32_t)__bfloat16_as_ushort(ah) | ((uint32_t)__bfloat16_as_ushort(bh) << 16);
}
__device__ __forceinline__ uint32_t packbf(float a, float b) {
    __nv_bfloat162 t = __floats2bfloat162_rn(a, b);
    return *reinterpret_cast<uint32_t*>(&t);
}

// ---------------------------------------------------------------------------
// R15 champion (194.7us) + ONE change: S-phase mma interleave widened from
// 2 to 4 independent accumulator chains (two n-tile groups' B-frags loaded
// together). Per-chain op order unchanged -> bitwise-identical results.
// CTA = (wh, qb): 128 q rows. 256 threads, 8 warps; 8 chunks of 64 keys.
// ---------------------------------------------------------------------------
__global__ __launch_bounds__(256, 2)
void fused_attn_mma(const float* __restrict__ qkv, const float* __restrict__ cw,
                    const float* __restrict__ cb, float* __restrict__ attn_out,
                    float* __restrict__ xout) {
    extern __shared__ char smem[];
    uint32_t sb = (uint32_t)__cvta_generic_to_shared(smem);
    float* Sr  = (float*)(smem + OFF_SR);
    float* Wsh = (float*)(smem + OFF_W);
    float* CBs = (float*)(smem + OFF_CB);
    float* Vf  = (float*)(smem + OFF_VF);

    int bx = blockIdx.x, wh = bx >> 2, qb = bx & 3;
    int n = wh >> 3, h = wh & 7, b = n >> 3, w2 = n & 7;
    int tid = threadIdx.x, lane = tid & 31, warp = tid >> 5;
    int g = lane >> 2, t = lane & 3;

    const float* Qg = qkv + (size_t)(0 + b) * 4096 * 256;
    const float* Kg = qkv + (size_t)(4 + b) * 4096 * 256;
    const float* Vg = qkv + (size_t)(8 + b) * 4096 * 256;

    // ---- prologue: Q hi/lo (QSCALE folded), V bf16, conv params ----
    {
        int row = tid >> 1, d0 = (tid & 1) * 16;
        int l = L_OF(qb * 128 + row);
        const float4* src = (const float4*)(Qg + (size_t)l * 256 + h * 32 + d0);
        uint32_t H[8], L[8];
        #pragma unroll
        for (int v4 = 0; v4 < 4; v4++) {
            float4 q = src[v4];
            q.x *= QSCALE; q.y *= QSCALE; q.z *= QSCALE; q.w *= QSCALE;
            H[2*v4]   = packpair(q.x, q.y, L[2*v4]);
            H[2*v4+1] = packpair(q.z, q.w, L[2*v4+1]);
        }
        char* qh = smem + OFF_QH + row * 80 + d0 * 2;
        char* ql = smem + OFF_QL + row * 80 + d0 * 2;
        *(uint4*)qh        = make_uint4(H[0], H[1], H[2], H[3]);
        *(uint4*)(qh + 16) = make_uint4(H[4], H[5], H[6], H[7]);
        *(uint4*)ql        = make_uint4(L[0], L[1], L[2], L[3]);
        *(uint4*)(ql + 16) = make_uint4(L[4], L[5], L[6], L[7]);
    }
    {   // V bf16 ch-major: warp covers 64 keys, lane = channel
        #pragma unroll 4
        for (int i = 0; i < 64; i += 2) {
            int k = warp * 64 + i;
            float v0 = Vg[(size_t)L_OF(k) * 256 + h * 32 + lane];
            float v1 = Vg[(size_t)L_OF(k + 1) * 256 + h * 32 + lane];
            *(uint32_t*)(smem + OFF_VT + lane * 1040 + k * 2) = packbf(v0, v1);
        }
    }
    for (int i = tid; i < 288; i += 256) Wsh[i] = cw[(h * 32) * 9 + i];
    if (tid < 32) CBs[tid] = cb[h * 32 + tid];

    // prefetch K chunk 0
    float4 pf0, pf1;
    {
        int krow = tid >> 2, d0 = (tid & 3) * 8;
        const float* p = Kg + (size_t)L_OF(krow) * 256 + h * 32 + d0;
        pf0 = *(const float4*)p; pf1 = *(const float4*)(p + 4);
    }
    __syncthreads();

    // Q A-frags (per warp, fixed)
    uint32_t aQh[2][4], aQl[2][4];
    {
        uint32_t laneQ = (uint32_t)((warp * 16 + (lane & 15)) * 80 + (lane >> 4) * 16);
        #pragma unroll
        for (int s = 0; s < 2; s++) {
            LDM4(aQh[s], sb + OFF_QH + s * 32 + laneQ);
            LDM4(aQl[s], sb + OFF_QL + s * 32 + laneQ);
        }
    }
    uint32_t laneK = (uint32_t)(((((lane >> 4) & 1) * 8) + (lane & 7)) * 80 + ((lane >> 3) & 1) * 16);
    uint32_t laneV = (uint32_t)(((((lane >> 4) & 1) * 8) + (lane & 7)) * 1040 + ((lane >> 3) & 1) * 16);

    float sumA = 0.f, sumB = 0.f;
    float oacc[4][4];
    #pragma unroll
    for (int i = 0; i < 4; i++)
        #pragma unroll
        for (int j = 0; j < 4; j++) oacc[i][j] = 0.f;

    float* attnp = attn_out + ((size_t)wh * 512 + qb * 128) * 512;

    for (int c = 0; c < 8; c++) {
        // stage prefetched K chunk (hi/lo split) — single sync per iteration
        uint32_t stg = OFF_KS + (uint32_t)(c & 1) * 10240u;
        {
            int krow = tid >> 2, d0b = (tid & 3) * 16;
            uint32_t H[4], L[4];
            H[0] = packpair(pf0.x, pf0.y, L[0]); H[1] = packpair(pf0.z, pf0.w, L[1]);
            H[2] = packpair(pf1.x, pf1.y, L[2]); H[3] = packpair(pf1.z, pf1.w, L[3]);
            *(uint4*)(smem + stg + krow * 80 + d0b)        = make_uint4(H[0], H[1], H[2], H[3]);
            *(uint4*)(smem + stg + 5120 + krow * 80 + d0b) = make_uint4(L[0], L[1], L[2], L[3]);
        }
        __syncthreads();
        if (c < 7) {
            int krow = tid >> 2, d0 = (tid & 3) * 8;
            const float* p = Kg + (size_t)L_OF((c + 1) * 64 + krow) * 256 + h * 32 + d0;
            pf0 = *(const float4*)p; pf1 = *(const float4*)(p + 4);
        }

        // ---- S chunk: 48 mmas, FOUR interleaved accumulator chains ----
        float sacc[8][4];
        #pragma unroll
        for (int i = 0; i < 8; i++)
            #pragma unroll
            for (int j = 0; j < 4; j++) sacc[i][j] = 0.f;
        uint32_t kh = sb + stg;
        #pragma unroll
        for (int s = 0; s < 2; s++) {
            #pragma unroll
            for (int gp = 0; gp < 2; gp++) {
                int nt0 = gp * 4;
                uint32_t bh0[4], bl0[4], bh1[4], bl1[4];
                LDM4(bh0, kh + (uint32_t)nt0 * 640 + s * 32 + laneK);
                LDM4(bl0, kh + 5120 + (uint32_t)nt0 * 640 + s * 32 + laneK);
                LDM4(bh1, kh + (uint32_t)(nt0 + 2) * 640 + s * 32 + laneK);
                LDM4(bl1, kh + 5120 + (uint32_t)(nt0 + 2) * 640 + s * 32 + laneK);
                MMA(sacc[nt0],     aQh[s], bh0);
                MMA(sacc[nt0 + 1], aQh[s], bh0 + 2);
                MMA(sacc[nt0 + 2], aQh[s], bh1);
                MMA(sacc[nt0 + 3], aQh[s], bh1 + 2);
                MMA(sacc[nt0],     aQh[s], bl0);
                MMA(sacc[nt0 + 1], aQh[s], bl0 + 2);
                MMA(sacc[nt0 + 2], aQh[s], bl1);
                MMA(sacc[nt0 + 3], aQh[s], bl1 + 2);
                MMA(sacc[nt0],     aQl[s], bh0);
                MMA(sacc[nt0 + 1], aQl[s], bh0 + 2);
                MMA(sacc[nt0 + 2], aQl[s], bh1);
                MMA(sacc[nt0 + 3], aQl[s], bh1 + 2);
            }
        }

        // ---- exp2 (in place) + rowsums + unnormalized attn STG ----
        #pragma unroll
        for (int nt = 0; nt < 8; nt++) {
            float e0, e1, e2, e3;
            EX2(e0, sacc[nt][0]); EX2(e1, sacc[nt][1]);
            EX2(e2, sacc[nt][2]); EX2(e3, sacc[nt][3]);
            sumA += e0 + e1; sumB += e2 + e3;
            sacc[nt][0] = e0; sacc[nt][1] = e1; sacc[nt][2] = e2; sacc[nt][3] = e3;
            float* p0 = attnp + (size_t)(warp * 16 + g) * 512 + c * 64 + nt * 8 + 2 * t;
            *(float2*)p0 = make_float2(e0, e1);
            *(float2*)(p0 + 8 * 512) = make_float2(e2, e3);
        }

        // ---- PV: S D-frags become A-frags; 16 mmas ----
        #pragma unroll
        for (int ks = 0; ks < 4; ks++) {
            uint32_t Ea[4] = {
                packbf(sacc[2*ks][0],   sacc[2*ks][1]),
                packbf(sacc[2*ks][2],   sacc[2*ks][3]),
                packbf(sacc[2*ks+1][0], sacc[2*ks+1][1]),
                packbf(sacc[2*ks+1][2], sacc[2*ks+1][3]) };
            uint32_t bv[4];
            LDM4(bv, sb + OFF_VT + (uint32_t)(c * 128 + ks * 32) + laneV);
            MMA(oacc[0], Ea, bv); MMA(oacc[1], Ea, bv + 2);
            LDM4(bv, sb + OFF_VT + 16640u + (uint32_t)(c * 128 + ks * 32) + laneV);
            MMA(oacc[2], Ea, bv); MMA(oacc[3], Ea, bv + 2);
        }
        // no bottom sync: 2-stage ring + top sync make it redundant
    }

    // ---- rowsum reduce across the 4 lanes sharing a row ----
    sumA += __shfl_xor_sync(0xffffffffu, sumA, 1);
    sumA += __shfl_xor_sync(0xffffffffu, sumA, 2);
    sumB += __shfl_xor_sync(0xffffffffu, sumB, 1);
    sumB += __shfl_xor_sync(0xffffffffu, sumB, 2);
    float invA = 1.0f / sumA, invB = 1.0f / sumB;
    if (t == 0) { Sr[warp * 16 + g] = invA; Sr[warp * 16 + 8 + g] = invB; }
    __syncthreads();                 // all compute done; Sr ready; smem dead

    // ---- fp32 V reload into aliased smem (for exact LePE conv) ----
    #pragma unroll 4
    for (int i = 0; i < 64; i++) {
        int k = warp * 64 + i;
        Vf[lane * 516 + k] = Vg[(size_t)L_OF(k) * 256 + h * 32 + lane];
    }
    // ---- attn in-place rescale (L2-hot; 2 lines/iter for MLP) ----
    #pragma unroll 4
    for (int j = 0; j < 32; j++) {
        int idx = tid + j * 512;
        int row0 = idx >> 7, c40 = idx & 127;
        int row1 = (idx + 256) >> 7, c41 = (idx + 256) & 127;
        float* p0 = attnp + (size_t)row0 * 512 + c40 * 4;
        float* p1 = attnp + (size_t)row1 * 512 + c41 * 4;
        float4 v0 = *(float4*)p0;
        float4 v1 = *(float4*)p1;
        float i0 = Sr[row0], i1 = Sr[row1];
        v0.x *= i0; v0.y *= i0; v0.z *= i0; v0.w *= i0;
        v1.x *= i1; v1.y *= i1; v1.z *= i1; v1.w *= i1;
        *(float4*)p0 = v0;
        *(float4*)p1 = v1;
    }
    __syncthreads();                 // Vf ready

    // ---- epilogue: O/sum + LePE conv + STG x ----
    #pragma unroll
    for (int rsel = 0; rsel < 2; rsel++) {
        int R = warp * 16 + g + rsel * 8;
        int tg = qb * 128 + R;
        int hs = tg >> 3, ws = tg & 7;
        float inv = rsel ? invB : invA;
        int l = hs * 64 + w2 * 8 + ws;
        float* xp = xout + ((size_t)b * 4096 + l) * 256 + h * 32;
        #pragma unroll
        for (int ct = 0; ct < 4; ct++) {
            int ch0 = ct * 8 + 2 * t;
            float o0 = oacc[ct][2 * rsel]     * inv + CBs[ch0];
            float o1 = oacc[ct][2 * rsel + 1] * inv + CBs[ch0 + 1];
            #pragma unroll
            for (int dy = -1; dy <= 1; dy++) {
                if ((unsigned)(hs + dy) >= 64u) continue;
                #pragma unroll
                for (int dx = -1; dx <= 1; dx++) {
                    if ((unsigned)(ws + dx) >= 8u) continue;
                    int kk = tg + dy * 8 + dx, wi = (dy + 1) * 3 + (dx + 1);
                    o0 += Vf[ch0 * 516 + kk]       * Wsh[ch0 * 9 + wi];
                    o1 += Vf[(ch0 + 1) * 516 + kk] * Wsh[(ch0 + 1) * 9 + wi];
                }
            }
            *(float2*)(xp + ch0) = make_float2(o0, o1);
        }
    }
}

// ---------------------------------------------------------------------------
extern "C" void kernel_launch(void* const* d_in, const int* in_sizes, int n_in,
                              void* d_out, int out_size) {
    const float* qkv = (const float*)d_in[0];
    const float* cw  = (const float*)d_in[1];
    const float* cb  = (const float*)d_in[2];
    float* xout = (float*)d_out;
    float* attn = xout + (size_t)4 * 4096 * 256;    // x first, then attn

    cudaFuncSetAttribute(fused_attn_mma,
                         cudaFuncAttributeMaxDynamicSharedMemorySize, SMEM_BYTES);
    fused_attn_mma<<<1024, 256, SMEM_BYTES>>>(qkv, cw, cb, attn, xout);
}